// round 1
// baseline (speedup 1.0000x reference)
#include <cuda_runtime.h>
#include <math.h>

#define Bn 32
#define Cn 16
#define Hn 128
#define Wn 128
#define TS 16

// Double-buffered recurrent state (parity = t&1). 16 MB total, device globals
// (no allocation allowed in kernel_launch).
__device__ float g_h[2][Bn * Hn * Wn * 2];
__device__ float g_c[2][Bn * Hn * Wn * 2];

__device__ __forceinline__ float sigm(float v) { return 1.0f / (1.0f + expf(-v)); }

__device__ __forceinline__ float block_sum256(float v, float* sred) {
    #pragma unroll
    for (int o = 16; o > 0; o >>= 1) v += __shfl_down_sync(0xffffffffu, v, o);
    int lane = threadIdx.x & 31, wid = threadIdx.x >> 5;
    if (lane == 0) sred[wid] = v;
    __syncthreads();
    if (wid == 0) {
        v = (lane < 8) ? sred[lane] : 0.0f;
        #pragma unroll
        for (int o = 4; o > 0; o >>= 1) v += __shfl_down_sync(0xffffffffu, v, o);
    }
    return v;  // valid in thread 0
}

__global__ void zero_out_kernel(float* out) {
    if (threadIdx.x < Bn) out[threadIdx.x] = 0.0f;
}

// Zeros parity-0 h/c state and accumulates the channel-0 log-prob term
// (p0 = broadcast b_out).
__global__ __launch_bounds__(256) void init_kernel(const float* __restrict__ x,
                                                   const float* __restrict__ b_out,
                                                   float* __restrict__ out) {
    __shared__ float sred[8];
    int idx = blockIdx.x * 256 + threadIdx.x;  // 0 .. B*H*W-1
    float2 z2 = make_float2(0.0f, 0.0f);
    ((float2*)g_h[0])[idx] = z2;
    ((float2*)g_c[0])[idx] = z2;

    int b = idx >> 14;        // / (128*128)
    int pix = idx & 16383;
    float xv = x[(size_t)(b * Cn + 0) * (Hn * Wn) + pix];
    float mu = b_out[0], ls = b_out[1];
    float e = expf(-ls);
    float z = (xv - mu) * e;
    float lp = -0.5f * z * z - ls - 0.9189385332046727f;

    float tot = block_sum256(lp, sred);
    if (threadIdx.x == 0) atomicAdd(&out[b], tot);
}

// One LSTM time step, fully fused per 16x16 tile:
//   zi = conv3x3(x_t, Win)            (computed at interior +-2)
//   ig = conv3x3(zi, Wih)             (at interior +-1, the extended region E)
//   gates = ig + conv3x3(h_old, Whh)  (h_old needed at interior +-2)
//   LSTM elementwise -> h_new, c_new  (h_new kept in smem over E for halo)
//   p = conv3x3(h_new, Wout_y)        (interior only)
//   lp vs x_{t+1}, block-reduced into out[b]
__global__ __launch_bounds__(256) void step_kernel(
    const float* __restrict__ x,
    const float* __restrict__ Win,  const float* __restrict__ b_in,
    const float* __restrict__ Wih,  const float* __restrict__ b_ih,
    const float* __restrict__ Whh,  const float* __restrict__ b_hh,
    const float* __restrict__ Wout, const float* __restrict__ b_out,
    float* __restrict__ out, int t)
{
    __shared__ float sx[22][24];        // x_t tile, offset (-3,-3)
    __shared__ float szi[20][24];       // zi, offset (-2,-2)
    __shared__ float sh[20][20][2];     // h_old, offset (-2,-2)
    __shared__ float shn[18][18][2];    // h_new, offset (-1,-1)
    __shared__ float sWin[9], sWih[72], sWhh[144], sWoutY[36];
    __shared__ float sbih[8], sbhh[8], sbout[2], sbin[1];
    __shared__ float sred[8];

    const int tid = threadIdx.x;
    const int b = blockIdx.z;
    const int gx0 = blockIdx.x * TS, gy0 = blockIdx.y * TS;
    const int p = t & 1;

    // ---- weights -> smem (HWIO layouts) ----
    if (tid < 144) sWhh[tid] = Whh[tid];
    if (tid < 72)  sWih[tid] = Wih[tid];
    if (tid < 36) {  // Wout_y = Wout[:,:,:2,:], src flat ((k)*4+ci)*2+co
        int k = tid >> 2, ci = (tid >> 1) & 1, co = tid & 1;
        sWoutY[tid] = Wout[(k * 4 + ci) * 2 + co];
    }
    if (tid < 9) sWin[tid] = Win[tid];
    if (tid < 8) { sbih[tid] = b_ih[tid]; sbhh[tid] = b_hh[tid]; }
    if (tid < 2) sbout[tid] = b_out[tid];
    if (tid == 0) sbin[0] = b_in[0];

    const float* xin = x + (size_t)(b * Cn + t) * (Hn * Wn);

    // ---- load x_t tile (22x22, zero-padded OOB) ----
    for (int i = tid; i < 22 * 22; i += 256) {
        int r = i / 22, c = i - r * 22;
        int gy = gy0 - 3 + r, gx = gx0 - 3 + c;
        float v = 0.0f;
        if ((unsigned)gy < Hn && (unsigned)gx < Wn) v = xin[gy * Wn + gx];
        sx[r][c] = v;
    }

    // ---- load h_old (20x20, zero-padded OOB) ----
    const float* hin = g_h[p] + (size_t)b * (Hn * Wn * 2);
    for (int i = tid; i < 20 * 20; i += 256) {
        int r = i / 20, c = i - r * 20;
        int gy = gy0 - 2 + r, gx = gx0 - 2 + c;
        float2 hv = make_float2(0.0f, 0.0f);
        if ((unsigned)gy < Hn && (unsigned)gx < Wn)
            hv = *(const float2*)(hin + (size_t)(gy * Wn + gx) * 2);
        sh[r][c][0] = hv.x; sh[r][c][1] = hv.y;
    }
    __syncthreads();

    // ---- zi = conv3x3(x, Win) at 20x20 (must be 0 at OOB positions: padding) ----
    {
        float bin = sbin[0];
        for (int i = tid; i < 20 * 20; i += 256) {
            int r = i / 20, c = i - r * 20;
            int gy = gy0 - 2 + r, gx = gx0 - 2 + c;
            float v = 0.0f;
            if ((unsigned)gy < Hn && (unsigned)gx < Wn) {
                v = bin;
                #pragma unroll
                for (int dy = 0; dy < 3; dy++)
                    #pragma unroll
                    for (int dx = 0; dx < 3; dx++)
                        v += sx[r + dy][c + dx] * sWin[dy * 3 + dx];
            }
            szi[r][c] = v;
        }
    }
    __syncthreads();

    // ---- gates + LSTM over extended 18x18 region ----
    const float* cin  = g_c[p]     + (size_t)b * (Hn * Wn * 2);
    float* hout       = g_h[1 - p] + (size_t)b * (Hn * Wn * 2);
    float* cout       = g_c[1 - p] + (size_t)b * (Hn * Wn * 2);

    for (int i = tid; i < 18 * 18; i += 256) {
        int r = i / 18, c = i - r * 18;
        int gy = gy0 - 1 + r, gx = gx0 - 1 + c;
        float hn0 = 0.0f, hn1 = 0.0f;
        if ((unsigned)gy < Hn && (unsigned)gx < Wn) {
            float acc[8];
            #pragma unroll
            for (int f = 0; f < 8; f++) acc[f] = sbih[f] + sbhh[f];
            #pragma unroll
            for (int dy = 0; dy < 3; dy++) {
                #pragma unroll
                for (int dx = 0; dx < 3; dx++) {
                    float zv = szi[r + dy][c + dx];
                    float h0 = sh[r + dy][c + dx][0];
                    float h1 = sh[r + dy][c + dx][1];
                    const float* w1 = &sWih[(dy * 3 + dx) * 8];
                    const float* w2 = &sWhh[(dy * 3 + dx) * 16];
                    #pragma unroll
                    for (int f = 0; f < 8; f++)
                        acc[f] += zv * w1[f] + h0 * w2[f] + h1 * w2[8 + f];
                }
            }
            float2 cold = *(const float2*)(cin + (size_t)(gy * Wn + gx) * 2);
            float ii0 = sigm(acc[0]),        ii1 = sigm(acc[1]);
            float gg0 = tanhf(acc[2]),       gg1 = tanhf(acc[3]);
            float ff0 = sigm(acc[4] + 1.0f), ff1 = sigm(acc[5] + 1.0f);
            float oo0 = sigm(acc[6]),        oo1 = sigm(acc[7]);
            float cn0 = ff0 * cold.x + ii0 * gg0;
            float cn1 = ff1 * cold.y + ii1 * gg1;
            hn0 = oo0 * tanhf(cn0);
            hn1 = oo1 * tanhf(cn1);
            if (r >= 1 && r < 17 && c >= 1 && c < 17) {  // interior -> persist state
                *(float2*)(hout + (size_t)(gy * Wn + gx) * 2) = make_float2(hn0, hn1);
                *(float2*)(cout + (size_t)(gy * Wn + gx) * 2) = make_float2(cn0, cn1);
            }
        }
        shn[r][c][0] = hn0; shn[r][c][1] = hn1;
    }
    __syncthreads();

    // ---- p = conv3x3(h_new, Wout_y); log-prob vs x channel t+1 ----
    int iy = tid >> 4, ix = tid & 15;
    float p0 = sbout[0], p1 = sbout[1];
    #pragma unroll
    for (int dy = 0; dy < 3; dy++) {
        #pragma unroll
        for (int dx = 0; dx < 3; dx++) {
            float h0 = shn[iy + dy][ix + dx][0];
            float h1 = shn[iy + dy][ix + dx][1];
            const float* w = &sWoutY[(dy * 3 + dx) * 4];  // [ci][co]
            p0 += h0 * w[0] + h1 * w[2];
            p1 += h0 * w[1] + h1 * w[3];
        }
    }
    const float* xnext = x + (size_t)(b * Cn + t + 1) * (Hn * Wn);
    float xv = xnext[(gy0 + iy) * Wn + (gx0 + ix)];
    float e = expf(-p1);
    float z = (xv - p0) * e;
    float lp = -0.5f * z * z - p1 - 0.9189385332046727f;

    float tot = block_sum256(lp, sred);
    if (tid == 0) atomicAdd(&out[b], tot);
}

extern "C" void kernel_launch(void* const* d_in, const int* in_sizes, int n_in,
                              void* d_out, int out_size) {
    const float* x     = (const float*)d_in[0];
    const float* Win   = (const float*)d_in[1];
    const float* b_in  = (const float*)d_in[2];
    const float* Wih   = (const float*)d_in[3];
    const float* b_ih  = (const float*)d_in[4];
    const float* Whh   = (const float*)d_in[5];
    const float* b_hh  = (const float*)d_in[6];
    const float* Wout  = (const float*)d_in[7];
    const float* b_out = (const float*)d_in[8];
    float* out = (float*)d_out;

    zero_out_kernel<<<1, 32>>>(out);
    init_kernel<<<(Bn * Hn * Wn) / 256, 256>>>(x, b_out, out);

    dim3 grid(Wn / TS, Hn / TS, Bn);
    for (int t = 0; t < Cn - 1; t++) {
        step_kernel<<<grid, 256>>>(x, Win, b_in, Wih, b_ih, Whh, b_hh,
                                   Wout, b_out, out, t);
    }
}

// round 2
// speedup vs baseline: 2.4960x; 2.4960x over previous
#include <cuda_runtime.h>
#include <math.h>

#define Bn 32
#define Cn 16
#define Hn 128
#define Wn 128
#define TSX 32
#define TSY 32

// Double-buffered recurrent state (parity = t&1). 16 MB total.
__device__ float g_h[2][Bn * Hn * Wn * 2];
__device__ float g_c[2][Bn * Hn * Wn * 2];

__device__ __forceinline__ float tanh_fast(float x) {
    float y;
    asm("tanh.approx.f32 %0, %1;" : "=f"(y) : "f"(x));
    return y;
}
__device__ __forceinline__ float sigm(float v) {
    return fmaf(tanh_fast(0.5f * v), 0.5f, 0.5f);
}

__device__ __forceinline__ float block_sum256(float v, float* sred) {
    #pragma unroll
    for (int o = 16; o > 0; o >>= 1) v += __shfl_down_sync(0xffffffffu, v, o);
    int lane = threadIdx.x & 31, wid = threadIdx.x >> 5;
    if (lane == 0) sred[wid] = v;
    __syncthreads();
    if (wid == 0) {
        v = (lane < 8) ? sred[lane] : 0.0f;
        #pragma unroll
        for (int o = 4; o > 0; o >>= 1) v += __shfl_down_sync(0xffffffffu, v, o);
    }
    return v;  // valid in thread 0
}

__global__ void zero_out_kernel(float* out) {
    if (threadIdx.x < Bn) out[threadIdx.x] = 0.0f;
}

// Zeros parity-0 h/c state and accumulates the channel-0 log-prob term.
__global__ __launch_bounds__(256) void init_kernel(const float* __restrict__ x,
                                                   const float* __restrict__ b_out,
                                                   float* __restrict__ out) {
    __shared__ float sred[8];
    int idx = blockIdx.x * 256 + threadIdx.x;  // 0 .. B*H*W-1
    float2 z2 = make_float2(0.0f, 0.0f);
    ((float2*)g_h[0])[idx] = z2;
    ((float2*)g_c[0])[idx] = z2;

    int b = idx >> 14;
    int pix = idx & 16383;
    float xv = x[(size_t)(b * Cn + 0) * (Hn * Wn) + pix];
    float mu = b_out[0], ls = b_out[1];
    float e = __expf(-ls);
    float z = (xv - mu) * e;
    float lp = -0.5f * z * z - ls - 0.9189385332046727f;

    float tot = block_sum256(lp, sred);
    if (threadIdx.x == 0) atomicAdd(&out[b], tot);
}

// One LSTM time step fused per 32x32 tile (256 threads, 4 px/thread):
//   zi = conv3x3(x_t, Win)   over 36x36 (-2,-2)
//   gates = conv3x3(zi,Wih)+conv3x3(h_old,Whh) -> LSTM over 34x34 (-1,-1)
//   p = conv3x3(h_new, Wout_y) over 32x32 interior; log-prob reduce
__global__ __launch_bounds__(256, 2) void step_kernel(
    const float* __restrict__ x,
    const float* __restrict__ Win,  const float* __restrict__ b_in,
    const float* __restrict__ Wih,  const float* __restrict__ b_ih,
    const float* __restrict__ Whh,  const float* __restrict__ b_hh,
    const float* __restrict__ Wout, const float* __restrict__ b_out,
    float* __restrict__ out, int t)
{
    __shared__ float sx[38 * 38];         // x_t, offset (-3,-3)
    __shared__ float szi[36 * 36];        // zi,  offset (-2,-2)
    __shared__ float sh0[36 * 36];        // h_old ch0, offset (-2,-2)
    __shared__ float sh1[36 * 36];        // h_old ch1
    __shared__ float shn0[34 * 34];       // h_new ch0, offset (-1,-1)
    __shared__ float shn1[34 * 34];       // h_new ch1
    __shared__ float sWin[9], sWih[72], sWhh[144], sWoutY[36];
    __shared__ float sbih[8], sbhh[8], sbout[2], sbin[1];
    __shared__ float sred[8];

    const int tid = threadIdx.x;
    const int b = blockIdx.z;
    const int gx0 = blockIdx.x * TSX, gy0 = blockIdx.y * TSY;
    const int p = t & 1;

    // ---- weights -> smem ----
    if (tid < 144) sWhh[tid] = Whh[tid];
    if (tid < 72)  sWih[tid] = Wih[tid];
    if (tid < 36) {  // Wout_y = Wout[:,:,:2,:], src flat (k*4+ci)*2+co
        int k = tid >> 2, ci = (tid >> 1) & 1, co = tid & 1;
        sWoutY[tid] = Wout[(k * 4 + ci) * 2 + co];
    }
    if (tid < 9) sWin[tid] = Win[tid];
    if (tid < 8) { sbih[tid] = b_ih[tid]; sbhh[tid] = b_hh[tid]; }
    if (tid < 2) sbout[tid] = b_out[tid];
    if (tid == 0) sbin[0] = b_in[0];

    const float* xin = x + (size_t)(b * Cn + t) * (Hn * Wn);

    // ---- load x_t tile (38x38, zero-padded OOB) ----
    for (int i = tid; i < 38 * 38; i += 256) {
        int r = i / 38, c = i - r * 38;
        int gy = gy0 - 3 + r, gx = gx0 - 3 + c;
        float v = 0.0f;
        if ((unsigned)gy < Hn && (unsigned)gx < Wn) v = xin[gy * Wn + gx];
        sx[i] = v;
    }

    // ---- load h_old (36x36, zero-padded OOB) ----
    const float* hin = g_h[p] + (size_t)b * (Hn * Wn * 2);
    for (int i = tid; i < 36 * 36; i += 256) {
        int r = i / 36, c = i - r * 36;
        int gy = gy0 - 2 + r, gx = gx0 - 2 + c;
        float2 hv = make_float2(0.0f, 0.0f);
        if ((unsigned)gy < Hn && (unsigned)gx < Wn)
            hv = *(const float2*)(hin + (size_t)(gy * Wn + gx) * 2);
        sh0[i] = hv.x; sh1[i] = hv.y;
    }
    __syncthreads();

    // ---- zi = conv3x3(x, Win) over 36x36 (0 at OOB: SAME padding) ----
    {
        float bin = sbin[0];
        for (int i = tid; i < 36 * 36; i += 256) {
            int r = i / 36, c = i - r * 36;
            int gy = gy0 - 2 + r, gx = gx0 - 2 + c;
            float v = 0.0f;
            if ((unsigned)gy < Hn && (unsigned)gx < Wn) {
                v = bin;
                #pragma unroll
                for (int dy = 0; dy < 3; dy++)
                    #pragma unroll
                    for (int dx = 0; dx < 3; dx++)
                        v += sx[(r + dy) * 38 + (c + dx)] * sWin[dy * 3 + dx];
            }
            szi[i] = v;
        }
    }
    __syncthreads();

    // ---- gates + LSTM over extended 34x34 region ----
    const float* cin  = g_c[p]     + (size_t)b * (Hn * Wn * 2);
    float* hout       = g_h[1 - p] + (size_t)b * (Hn * Wn * 2);
    float* cout       = g_c[1 - p] + (size_t)b * (Hn * Wn * 2);

    for (int i = tid; i < 34 * 34; i += 256) {
        int r = i / 34, c = i - r * 34;
        int gy = gy0 - 1 + r, gx = gx0 - 1 + c;
        float hn0 = 0.0f, hn1 = 0.0f;
        if ((unsigned)gy < Hn && (unsigned)gx < Wn) {
            float acc[8];
            #pragma unroll
            for (int f = 0; f < 8; f++) acc[f] = sbih[f] + sbhh[f];
            #pragma unroll
            for (int dy = 0; dy < 3; dy++) {
                #pragma unroll
                for (int dx = 0; dx < 3; dx++) {
                    int si = (r + dy) * 36 + (c + dx);
                    float zv = szi[si];
                    float h0 = sh0[si];
                    float h1 = sh1[si];
                    const float* w1 = &sWih[(dy * 3 + dx) * 8];
                    const float* w2 = &sWhh[(dy * 3 + dx) * 16];
                    #pragma unroll
                    for (int f = 0; f < 8; f++)
                        acc[f] += zv * w1[f] + h0 * w2[f] + h1 * w2[8 + f];
                }
            }
            float2 cold = *(const float2*)(cin + (size_t)(gy * Wn + gx) * 2);
            float ii0 = sigm(acc[0]),            ii1 = sigm(acc[1]);
            float gg0 = tanh_fast(acc[2]),       gg1 = tanh_fast(acc[3]);
            float ff0 = sigm(acc[4] + 1.0f),     ff1 = sigm(acc[5] + 1.0f);
            float oo0 = sigm(acc[6]),            oo1 = sigm(acc[7]);
            float cn0 = ff0 * cold.x + ii0 * gg0;
            float cn1 = ff1 * cold.y + ii1 * gg1;
            hn0 = oo0 * tanh_fast(cn0);
            hn1 = oo1 * tanh_fast(cn1);
            if (r >= 1 && r < 33 && c >= 1 && c < 33) {  // interior -> persist
                *(float2*)(hout + (size_t)(gy * Wn + gx) * 2) = make_float2(hn0, hn1);
                *(float2*)(cout + (size_t)(gy * Wn + gx) * 2) = make_float2(cn0, cn1);
            }
        }
        shn0[i] = hn0; shn1[i] = hn1;
    }
    __syncthreads();

    // ---- p = conv3x3(h_new, Wout_y); log-prob vs x channel t+1 ----
    const float* xnext = x + (size_t)(b * Cn + t + 1) * (Hn * Wn);
    float lpacc = 0.0f;
    #pragma unroll
    for (int it = 0; it < 4; it++) {
        int i = tid + it * 256;          // 0..1023 interior pixel
        int iy = i >> 5, ix = i & 31;
        float p0 = sbout[0], p1 = sbout[1];
        #pragma unroll
        for (int dy = 0; dy < 3; dy++) {
            #pragma unroll
            for (int dx = 0; dx < 3; dx++) {
                int si = (iy + dy) * 34 + (ix + dx);
                float h0 = shn0[si];
                float h1 = shn1[si];
                const float* w = &sWoutY[(dy * 3 + dx) * 4];  // [ci][co]
                p0 += h0 * w[0] + h1 * w[2];
                p1 += h0 * w[1] + h1 * w[3];
            }
        }
        float xv = xnext[(gy0 + iy) * Wn + (gx0 + ix)];
        float e = __expf(-p1);
        float z = (xv - p0) * e;
        lpacc += -0.5f * z * z - p1 - 0.9189385332046727f;
    }

    float tot = block_sum256(lpacc, sred);
    if (tid == 0) atomicAdd(&out[b], tot);
}

extern "C" void kernel_launch(void* const* d_in, const int* in_sizes, int n_in,
                              void* d_out, int out_size) {
    const float* x     = (const float*)d_in[0];
    const float* Win   = (const float*)d_in[1];
    const float* b_in  = (const float*)d_in[2];
    const float* Wih   = (const float*)d_in[3];
    const float* b_ih  = (const float*)d_in[4];
    const float* Whh   = (const float*)d_in[5];
    const float* b_hh  = (const float*)d_in[6];
    const float* Wout  = (const float*)d_in[7];
    const float* b_out = (const float*)d_in[8];
    float* out = (float*)d_out;

    zero_out_kernel<<<1, 32>>>(out);
    init_kernel<<<(Bn * Hn * Wn) / 256, 256>>>(x, b_out, out);

    dim3 grid(Wn / TSX, Hn / TSY, Bn);
    for (int t = 0; t < Cn - 1; t++) {
        step_kernel<<<grid, 256>>>(x, Win, b_in, Wih, b_ih, Whh, b_hh,
                                   Wout, b_out, out, t);
    }
}

// round 3
// speedup vs baseline: 2.7155x; 1.0879x over previous
#include <cuda_runtime.h>
#include <math.h>

#define Bn 32
#define Cn 16
#define Hn 128
#define Wn 128
#define HW (Hn * Wn)
#define TX 64
#define TY 32
#define NB 256          // total blocks = (128/64)*(128/32)*32

#define EXH (TY + 2)    // 34
#define EXW (TX + 2)    // 66
#define SXH (TY + 4)    // 36
#define SXW (TX + 4)    // 68

// Double-buffered h state (parity = (t+1)&1). c never touches global.
__device__ float g_h[2][Bn * HW * 2];
__device__ unsigned g_arrive;
__device__ unsigned g_gen;

typedef unsigned long long u64;

__device__ __forceinline__ u64 ffma2(u64 a, u64 b, u64 c) {
    u64 d;
    asm("fma.rn.f32x2 %0, %1, %2, %3;" : "=l"(d) : "l"(a), "l"(b), "l"(c));
    return d;
}
__device__ __forceinline__ u64 pack2(float v) {
    u64 r;
    asm("mov.b64 %0, {%1, %1};" : "=l"(r) : "f"(v));
    return r;
}
__device__ __forceinline__ u64 pack2f(float a, float b) {
    u64 r;
    asm("mov.b64 %0, {%1, %2};" : "=l"(r) : "f"(a), "f"(b));
    return r;
}
__device__ __forceinline__ void unpack2(u64 v, float& lo, float& hi) {
    asm("mov.b64 {%0, %1}, %2;" : "=f"(lo), "=f"(hi) : "l"(v));
}
__device__ __forceinline__ float tanh_fast(float x) {
    float y;
    asm("tanh.approx.f32 %0, %1;" : "=f"(y) : "f"(x));
    return y;
}
__device__ __forceinline__ float sigm(float v) {
    return fmaf(tanh_fast(0.5f * v), 0.5f, 0.5f);
}

__device__ __forceinline__ void grid_barrier() {
    __syncthreads();
    if (threadIdx.x == 0) {
        __threadfence();
        unsigned gen = *(volatile unsigned*)&g_gen;   // read BEFORE arriving
        if (atomicAdd(&g_arrive, 1u) == NB - 1) {
            g_arrive = 0;
            __threadfence();
            atomicAdd(&g_gen, 1u);
        } else {
            while (*(volatile unsigned*)&g_gen == gen) { __nanosleep(64); }
        }
        __threadfence();
    }
    __syncthreads();
}

__device__ __forceinline__ float block_sum256(float v, float* sred) {
    #pragma unroll
    for (int o = 16; o > 0; o >>= 1) v += __shfl_down_sync(0xffffffffu, v, o);
    int lane = threadIdx.x & 31, wid = threadIdx.x >> 5;
    if (lane == 0) sred[wid] = v;
    __syncthreads();
    if (wid == 0) {
        v = (lane < 8) ? sred[lane] : 0.0f;
        #pragma unroll
        for (int o = 4; o > 0; o >>= 1) v += __shfl_down_sync(0xffffffffu, v, o);
    }
    return v;  // valid in thread 0
}

__global__ void zero_out_kernel(float* out) {
    if (threadIdx.x < Bn) out[threadIdx.x] = 0.0f;
}

// Persistent fused ConvLSTM: each block owns a 64x32 tile of one batch image
// and runs all 15 time steps, grid-barriering between steps.
__global__ __launch_bounds__(256, 2) void lstm_kernel(
    const float* __restrict__ x,
    const float* __restrict__ Win,  const float* __restrict__ b_in,
    const float* __restrict__ Wih,  const float* __restrict__ b_ih,
    const float* __restrict__ Whh,  const float* __restrict__ b_hh,
    const float* __restrict__ Wout, const float* __restrict__ b_out,
    float* __restrict__ out)
{
    __shared__ __align__(16) float sWih[72];    // [tap][8] -> u64 pairs [tap*4+fp]
    __shared__ __align__(16) float sWhh[144];   // [tap][16] -> u64 [tap*8 + (0..3 | 4..7)]
    __shared__ __align__(16) float sWoutY[36];  // [tap][ci][co] -> u64 [tap*2+ci]
    __shared__ __align__(16) float sbias[8];    // b_ih + b_hh
    __shared__ float sWin[9];
    __shared__ float sbin[1], sbout[2];
    __shared__ float sx[SXH * SXW];             // x_t, offset (-2,-2)
    __shared__ float szi[EXH * EXW];            // zi,  offset (-1,-1)
    __shared__ float sh0[EXH * EXW];            // h,   offset (-1,-1)
    __shared__ float sh1[EXH * EXW];
    __shared__ float sred[8];

    const int tid = threadIdx.x;
    const int b = blockIdx.z;
    const int gx0 = blockIdx.x * TX, gy0 = blockIdx.y * TY;
    const int ix = tid & 63;                 // column within tile
    const int iyg = (tid >> 6) << 3;         // first of 8 rows handled

    // ---- weights -> smem (once) ----
    if (tid < 144) sWhh[tid] = Whh[tid];
    if (tid < 72)  sWih[tid] = Wih[tid];
    if (tid < 36) {  // Wout_y = Wout[:,:,:2,:], src flat (k*4+ci)*2+co
        int k = tid >> 2, ci = (tid >> 1) & 1, co = tid & 1;
        sWoutY[tid] = Wout[(k * 4 + ci) * 2 + co];
    }
    if (tid < 9) sWin[tid] = Win[tid];
    if (tid < 8) sbias[tid] = b_ih[tid] + b_hh[tid];
    if (tid < 2) sbout[tid] = b_out[tid];
    if (tid == 0) sbin[0] = b_in[0];
    // h_0 = 0
    for (int i = tid; i < EXH * EXW; i += 256) { sh0[i] = 0.0f; sh1[i] = 0.0f; }

    float c0[8], c1[8];
    #pragma unroll
    for (int k = 0; k < 8; k++) { c0[k] = 0.0f; c1[k] = 0.0f; }

    __syncthreads();
    const u64* w1p = (const u64*)sWih;
    const u64* w2p = (const u64*)sWhh;
    const u64* wop = (const u64*)sWoutY;
    const u64* sbp = (const u64*)sbias;
    const u64 pbias = pack2f(sbout[0], sbout[1]);

    // ---- channel 0 log-prob: p0 = broadcast b_out ----
    float lpacc = 0.0f;
    {
        const float* x0 = x + (size_t)(b * Cn) * HW;
        float mu = sbout[0], ls = sbout[1];
        float e = __expf(-ls);
        #pragma unroll
        for (int k = 0; k < 8; k++) {
            float xv = x0[(gy0 + iyg + k) * Wn + gx0 + ix];
            float z = (xv - mu) * e;
            lpacc += -0.5f * z * z - ls - 0.9189385332046727f;
        }
    }

    for (int t = 0; t < 15; t++) {
        const float* xin = x + (size_t)(b * Cn + t) * HW;

        // (a) x_t tile 36x68, zero-padded OOB
        for (int i = tid; i < SXH * SXW; i += 256) {
            int r = i / SXW, c = i - r * SXW;
            int gy = gy0 - 2 + r, gx = gx0 - 2 + c;
            float v = 0.0f;
            if ((unsigned)gy < Hn && (unsigned)gx < Wn) v = xin[gy * Wn + gx];
            sx[i] = v;
        }
        __syncthreads();

        // (c) zi = conv3x3(x, Win) over 34x66 (0 at out-of-image)
        {
            float bin = sbin[0];
            for (int i = tid; i < EXH * EXW; i += 256) {
                int r = i / EXW, c = i - r * EXW;
                int gy = gy0 - 1 + r, gx = gx0 - 1 + c;
                float v = 0.0f;
                if ((unsigned)gy < Hn && (unsigned)gx < Wn) {
                    v = bin;
                    #pragma unroll
                    for (int dy = 0; dy < 3; dy++)
                        #pragma unroll
                        for (int dx = 0; dx < 3; dx++)
                            v += sx[(r + dy) * SXW + (c + dx)] * sWin[dy * 3 + dx];
                }
                szi[i] = v;
            }
        }
        __syncthreads();

        // (e) gates + LSTM, interior only (8 px per thread); c in registers
        {
            float2* hout = (float2*)(g_h[(t + 1) & 1] + (size_t)b * HW * 2);
            #pragma unroll
            for (int k = 0; k < 8; k++) {
                int iy = iyg + k;
                u64 a0 = sbp[0], a1 = sbp[1], a2 = sbp[2], a3 = sbp[3];
                #pragma unroll
                for (int dy = 0; dy < 3; dy++) {
                    #pragma unroll
                    for (int dx = 0; dx < 3; dx++) {
                        int si = (iy + dy) * EXW + ix + dx;
                        int tap = dy * 3 + dx;
                        u64 zp  = pack2(szi[si]);
                        u64 h0p = pack2(sh0[si]);
                        u64 h1p = pack2(sh1[si]);
                        a0 = ffma2(zp,  w1p[tap * 4 + 0], a0);
                        a1 = ffma2(zp,  w1p[tap * 4 + 1], a1);
                        a2 = ffma2(zp,  w1p[tap * 4 + 2], a2);
                        a3 = ffma2(zp,  w1p[tap * 4 + 3], a3);
                        a0 = ffma2(h0p, w2p[tap * 8 + 0], a0);
                        a1 = ffma2(h0p, w2p[tap * 8 + 1], a1);
                        a2 = ffma2(h0p, w2p[tap * 8 + 2], a2);
                        a3 = ffma2(h0p, w2p[tap * 8 + 3], a3);
                        a0 = ffma2(h1p, w2p[tap * 8 + 4], a0);
                        a1 = ffma2(h1p, w2p[tap * 8 + 5], a1);
                        a2 = ffma2(h1p, w2p[tap * 8 + 6], a2);
                        a3 = ffma2(h1p, w2p[tap * 8 + 7], a3);
                    }
                }
                float i0, i1, g0, g1, f0, f1, o0, o1;
                unpack2(a0, i0, i1); unpack2(a1, g0, g1);
                unpack2(a2, f0, f1); unpack2(a3, o0, o1);
                float cn0 = sigm(f0 + 1.0f) * c0[k] + sigm(i0) * tanh_fast(g0);
                float cn1 = sigm(f1 + 1.0f) * c1[k] + sigm(i1) * tanh_fast(g1);
                c0[k] = cn0; c1[k] = cn1;
                float hn0 = sigm(o0) * tanh_fast(cn0);
                float hn1 = sigm(o1) * tanh_fast(cn1);
                hout[(gy0 + iy) * Wn + gx0 + ix] = make_float2(hn0, hn1);
            }
        }

        grid_barrier();   // all h_{t+1} interior writes visible everywhere

        // (g) load h_{t+1} extended 34x66 (halo from neighbor blocks)
        {
            const float* hin = g_h[(t + 1) & 1] + (size_t)b * HW * 2;
            for (int i = tid; i < EXH * EXW; i += 256) {
                int r = i / EXW, c = i - r * EXW;
                int gy = gy0 - 1 + r, gx = gx0 - 1 + c;
                float2 hv = make_float2(0.0f, 0.0f);
                if ((unsigned)gy < Hn && (unsigned)gx < Wn)
                    hv = *(const float2*)(hin + (size_t)(gy * Wn + gx) * 2);
                sh0[i] = hv.x; sh1[i] = hv.y;
            }
        }
        __syncthreads();

        // (i) p = conv3x3(h_{t+1}, Wout_y); log-prob vs x channel t+1
        {
            const float* xnext = x + (size_t)(b * Cn + t + 1) * HW;
            #pragma unroll
            for (int k = 0; k < 8; k++) {
                int iy = iyg + k;
                u64 pp = pbias;
                #pragma unroll
                for (int dy = 0; dy < 3; dy++) {
                    #pragma unroll
                    for (int dx = 0; dx < 3; dx++) {
                        int si = (iy + dy) * EXW + ix + dx;
                        int tap = dy * 3 + dx;
                        pp = ffma2(pack2(sh0[si]), wop[tap * 2 + 0], pp);
                        pp = ffma2(pack2(sh1[si]), wop[tap * 2 + 1], pp);
                    }
                }
                float p0, p1;
                unpack2(pp, p0, p1);
                float xv = xnext[(gy0 + iy) * Wn + gx0 + ix];
                float e = __expf(-p1);
                float z = (xv - p0) * e;
                lpacc += -0.5f * z * z - p1 - 0.9189385332046727f;
            }
        }
        // next iteration's sx store is fenced by the sync after it; sh stays
        // valid until after next barrier.
    }

    float tot = block_sum256(lpacc, sred);
    if (tid == 0) atomicAdd(&out[b], tot);
}

extern "C" void kernel_launch(void* const* d_in, const int* in_sizes, int n_in,
                              void* d_out, int out_size) {
    const float* x     = (const float*)d_in[0];
    const float* Win   = (const float*)d_in[1];
    const float* b_in  = (const float*)d_in[2];
    const float* Wih   = (const float*)d_in[3];
    const float* b_ih  = (const float*)d_in[4];
    const float* Whh   = (const float*)d_in[5];
    const float* b_hh  = (const float*)d_in[6];
    const float* Wout  = (const float*)d_in[7];
    const float* b_out = (const float*)d_in[8];
    float* out = (float*)d_out;

    zero_out_kernel<<<1, 32>>>(out);

    dim3 grid(Wn / TX, Hn / TY, Bn);   // 2 x 4 x 32 = 256 blocks, all co-resident
    lstm_kernel<<<grid, 256>>>(x, Win, b_in, Wih, b_ih, Whh, b_hh,
                               Wout, b_out, out);
}